// round 14
// baseline (speedup 1.0000x reference)
#include <cuda_runtime.h>
#include <math.h>

#define NPTS   8192
#define TPB    512
#define QPT    8                 // queries per thread (4 packed f32x2 pairs)
#define QTILE  (TPB*QPT)         // 4096 queries per block
#define NTILE  (NPTS/QTILE)      // 2
#define NSEG   32                // db segments
#define SEGPTS (NPTS/NSEG)       // 256
#define NBLK   (NTILE*NSEG*4)    // 256 blocks (2/SM)

// Scratch (no allocs allowed)
__device__ float        g_pmin[4][NSEG][NPTS]; // [dir+2*part][seg][query] = qnorm+min
__device__ unsigned int g_count;               // zero-init; tail resets -> replay-safe

__device__ __forceinline__ unsigned long long pack2(float lo, float hi) {
    unsigned long long r;
    asm("mov.b64 %0, {%1, %2};" : "=l"(r)
        : "r"(__float_as_uint(lo)), "r"(__float_as_uint(hi)));
    return r;
}
__device__ __forceinline__ unsigned long long fma2(unsigned long long a,
                                                   unsigned long long b,
                                                   unsigned long long c) {
    unsigned long long d;
    asm("fma.rn.f32x2 %0, %1, %2, %3;" : "=l"(d) : "l"(a), "l"(b), "l"(c));
    return d;
}

// ---------------------------------------------------------------------------
// grid (NTILE*NSEG, dir, part) = 256 blocks of 512 thr (2/SM, 8 warps/SMSP).
// R13's f32x2 loop was latency-bound at 4 warps/SMSP (issue 48%, fma 27%):
// per-SMSP issue demand ~53K cyc vs ~150K measured. Doubling warps/SMSP fills
// the slack; qn[] moves to smem so regs fit the 64-reg/thread occupancy-2 cap.
// Per db point: 2 broadcast LDS.128 + 12 FFMA2 (24 MACs) + 4 mov + 8 FMNMX
// = 8 (query,point) pairs.
// dir0: query = T@cad, db = cam.  dir1: query = cam, db = T@cad.
// min_j |q-y|^2 = |q|^2 + min_j(|y|^2 - 2 q.y); -2 folded into staged coords.
// Ticket-elected last block merges db segments -> sqrt -> fp64 means.
// ---------------------------------------------------------------------------
__global__ void __launch_bounds__(TPB, 2)
k_fused(const float* __restrict__ cam, const float* __restrict__ cad,
        const float* __restrict__ xyz, const float* __restrict__ rpy,
        const float* __restrict__ quat, const float* __restrict__ bt,
        const float* __restrict__ theta, const float* __restrict__ pw,
        float* __restrict__ out)
{
    __shared__ float4 sA[SEGPTS];       // (-2x, -2x, -2y, -2y)
    __shared__ float4 sB[SEGPTS];       // (-2z, -2z,  w,   w)
    __shared__ float  s_qn[TPB * QPT];  // query norms (keeps regs under 64)
    __shared__ float  sxf[12];
    __shared__ double sr0[TPB], sr1[TPB];
    __shared__ int    s_last;

    const int part = blockIdx.z;
    const int dir  = blockIdx.y;
    const int tile = blockIdx.x >> 5;     // 0..1
    const int seg  = blockIdx.x & 31;     // 0..31
    const int tid  = threadIdx.x;
    const int dp   = dir + 2 * part;

    // --- per-block transform setup (thread 0; tiny) ---
    if (tid == 0) {
        float qa = quat[0], qb = quat[1], qc = quat[2], qd = quat[3];
        float qn = sqrtf(qa*qa + qb*qb + qc*qc + qd*qd);
        qa /= qn; qb /= qn; qc /= qn; qd /= qn;

        float B[16];
        B[0]  = 1.f - 2.f*qc*qc - 2.f*qd*qd;  B[1]  = 2.f*qb*qc - 2.f*qa*qd;        B[2]  = 2.f*qa*qc + 2.f*qb*qd;        B[3]  = bt[0];
        B[4]  = 2.f*qb*qc + 2.f*qa*qd;        B[5]  = 1.f - 2.f*qb*qb - 2.f*qd*qd;  B[6]  = 2.f*qc*qd - 2.f*qa*qb;        B[7]  = bt[1];
        B[8]  = 2.f*qb*qd - 2.f*qa*qc;        B[9]  = 2.f*qa*qb + 2.f*qc*qd;        B[10] = 1.f - 2.f*qb*qb - 2.f*qc*qc;  B[11] = bt[2];
        B[12] = 0.f; B[13] = 0.f; B[14] = 0.f; B[15] = 1.f;

        float ax = xyz[0], ay = xyz[1], az = xyz[2];
        float u  = rpy[0], v  = rpy[1], w  = rpy[2];
        float th = theta[0];
        float co = cosf(th), si = sinf(th), omc = 1.f - co;

        float R[16];
        R[0]  = u*u + (v*v + w*w)*co;   R[1]  = u*v*omc - w*si;          R[2]  = u*w*omc + v*si;
        R[3]  = (ax*(v*v + w*w) - u*(ay*v + az*w))*omc + (ay*w - az*v)*si;
        R[4]  = u*v*omc + w*si;         R[5]  = v*v + (u*u + w*w)*co;    R[6]  = v*w*omc - u*si;
        R[7]  = (ay*(u*u + w*w) - v*(ax*u + az*w))*omc + (az*u - ax*w)*si;
        R[8]  = u*w*omc - v*si;         R[9]  = v*w*omc + u*si;          R[10] = w*w + (u*u + v*v)*co;
        R[11] = (az*(u*u + v*v) - w*(ax*u + ay*v))*omc + (ax*v - ay*u)*si;
        R[12] = 0.f; R[13] = 0.f; R[14] = 0.f; R[15] = 1.f;

        float T[16];
        #pragma unroll
        for (int r = 0; r < 4; r++)
            #pragma unroll
            for (int c = 0; c < 4; c++) {
                float s = 0.f;
                #pragma unroll
                for (int k = 0; k < 4; k++) s += R[r*4 + k] * B[k*4 + c];
                T[r*4 + c] = s;
            }

        const float* X = (part == 0) ? B : T;
        #pragma unroll
        for (int i = 0; i < 12; i++) sxf[i] = X[i];

        if (blockIdx.x == 0 && dir == 0 && part == 0) {
            // out: [0]=all, [1]=base_obj, [2]=child_obj, [3..18]=base_T, [19..34]=rel_T
            #pragma unroll
            for (int i = 0; i < 16; i++) { out[3 + i] = B[i]; out[19 + i] = R[i]; }
        }
    }
    __syncthreads();

    const float t0 = sxf[0], t1 = sxf[1], t2  = sxf[2],  t3  = sxf[3];
    const float t4 = sxf[4], t5 = sxf[5], t6  = sxf[6],  t7  = sxf[7];
    const float t8 = sxf[8], t9 = sxf[9], t10 = sxf[10], t11 = sxf[11];

    const float* camP = cam + part * NPTS * 3;
    const float* cadP = cad + part * NPTS * 3;

    // --- stage this block's db segment, duplicated halves, -2 folded in ---
    for (int j = tid; j < SEGPTS; j += TPB) {
        int gj = seg * SEGPTS + j;
        float x, y, z;
        if (dir == 0) {
            x = camP[3*gj]; y = camP[3*gj + 1]; z = camP[3*gj + 2];
        } else {
            float a = cadP[3*gj], b = cadP[3*gj + 1], c = cadP[3*gj + 2];
            x = t0*a + t1*b + t2*c  + t3;
            y = t4*a + t5*b + t6*c  + t7;
            z = t8*a + t9*b + t10*c + t11;
        }
        float w  = x*x + y*y + z*z;
        float nx = -2.f*x, ny = -2.f*y, nz = -2.f*z;
        sA[j] = make_float4(nx, nx, ny, ny);
        sB[j] = make_float4(nz, nz, w,  w);
    }

    // --- load 8 queries, pack as 4 f32x2 pairs; norms go to smem ---
    float m[QPT];
    unsigned long long qx2[4], qy2[4], qz2[4];
    {
        float qx[QPT], qy[QPT], qz[QPT];
        #pragma unroll
        for (int k = 0; k < QPT; k++) {
            const int q = tile * QTILE + k * TPB + tid;
            const float* src = (dir == 0) ? cadP : camP;
            float x = src[3*q], y = src[3*q + 1], z = src[3*q + 2];
            if (dir == 0) {
                qx[k] = t0*x + t1*y + t2*z  + t3;
                qy[k] = t4*x + t5*y + t6*z  + t7;
                qz[k] = t8*x + t9*y + t10*z + t11;
            } else { qx[k] = x; qy[k] = y; qz[k] = z; }
            s_qn[k * TPB + tid] = qx[k]*qx[k] + qy[k]*qy[k] + qz[k]*qz[k];
            m[k]  = 3.4e38f;
        }
        #pragma unroll
        for (int p = 0; p < 4; p++) {
            qx2[p] = pack2(qx[2*p], qx[2*p + 1]);
            qy2[p] = pack2(qy[2*p], qy[2*p + 1]);
            qz2[p] = pack2(qz[2*p], qz[2*p + 1]);
        }
    }
    __syncthreads();

    // --- main loop: 2 LDS.128 feed 8 (query,point) pairs via 4 FFMA2 chains ---
    #pragma unroll 4
    for (int j = 0; j < SEGPTS; j++) {
        const ulonglong2 A = *reinterpret_cast<const ulonglong2*>(&sA[j]); // A.x=xx, A.y=yy
        const ulonglong2 B = *reinterpret_cast<const ulonglong2*>(&sB[j]); // B.x=zz, B.y=ww
        #pragma unroll
        for (int p = 0; p < 4; p++) {
            unsigned long long t = fma2(qz2[p], B.x, B.y);
            t = fma2(qy2[p], A.y, t);
            t = fma2(qx2[p], A.x, t);
            unsigned int lo, hi;
            asm("mov.b64 {%0, %1}, %2;" : "=r"(lo), "=r"(hi) : "l"(t));
            m[2*p]     = fminf(m[2*p],     __uint_as_float(lo));
            m[2*p + 1] = fminf(m[2*p + 1], __uint_as_float(hi));
        }
    }

    // partial results (can be tiny-negative; clamped in tail)
    #pragma unroll
    for (int k = 0; k < QPT; k++) {
        const int q = tile * QTILE + k * TPB + tid;
        g_pmin[dp][seg][q] = s_qn[k * TPB + tid] + m[k];
    }

    // --- ticket: last block reduces everything ---
    __threadfence();
    if (tid == 0) {
        unsigned int ticket = atomicAdd(&g_count, 1u);
        s_last = (ticket == NBLK - 1) ? 1 : 0;
    }
    __syncthreads();
    if (!s_last) return;

    __threadfence();
    double a0 = 0.0, a1 = 0.0;
    const int NG = NPTS / 4;                 // float4 groups per (dp,seg)
    for (int i = tid; i < 4 * NG; i += TPB) {
        const int d  = i / NG;
        const int qg = i % NG;
        const float4* base = reinterpret_cast<const float4*>(&g_pmin[d][0][0]);
        float4 v = base[qg];
        #pragma unroll
        for (int s = 1; s < NSEG; s++) {
            float4 u = base[s * NG + qg];
            v.x = fminf(v.x, u.x); v.y = fminf(v.y, u.y);
            v.z = fminf(v.z, u.z); v.w = fminf(v.w, u.w);
        }
        double dd = (double)sqrtf(fmaxf(v.x, 0.f))
                  + (double)sqrtf(fmaxf(v.y, 0.f))
                  + (double)sqrtf(fmaxf(v.z, 0.f))
                  + (double)sqrtf(fmaxf(v.w, 0.f));
        if (d < 2) a0 += dd; else a1 += dd;
    }
    sr0[tid] = a0; sr1[tid] = a1;
    __syncthreads();
    for (int s = TPB / 2; s > 0; s >>= 1) {
        if (tid < s) { sr0[tid] += sr0[tid + s]; sr1[tid] += sr1[tid + s]; }
        __syncthreads();
    }
    if (tid == 0) {
        double obj0 = sr0[0] / (double)NPTS;   // base part
        double obj1 = sr1[0] / (double)NPTS;   // child part
        out[1] = (float)obj0;
        out[2] = (float)obj1;
        out[0] = (float)(((double)pw[0] * obj0 + (double)pw[1] * obj1) / 2.0);
        g_count = 0;   // reset for next graph replay
    }
}

// ---------------------------------------------------------------------------
extern "C" void kernel_launch(void* const* d_in, const int* in_sizes, int n_in,
                              void* d_out, int out_size)
{
    const float* cam  = (const float*)d_in[0];  // camera_pts [2,8192,3]
    const float* cad  = (const float*)d_in[1];  // cad_pts    [2,8192,3]
    const float* xyz  = (const float*)d_in[2];  // [1,3]
    const float* rpy  = (const float*)d_in[3];  // [1,3]
    const float* pw   = (const float*)d_in[4];  // [2]
    const float* quat = (const float*)d_in[5];  // [4]
    const float* bt   = (const float*)d_in[6];  // [3,1]
    const float* th   = (const float*)d_in[7];  // [1]
    float* out = (float*)d_out;

    dim3 grid(NTILE * NSEG, 2, 2);   // 256 blocks of 512 thr (2 per SM)
    k_fused<<<grid, TPB>>>(cam, cad, xyz, rpy, quat, bt, th, pw, out);
}

// round 15
// speedup vs baseline: 1.0937x; 1.0937x over previous
#include <cuda_runtime.h>
#include <math.h>

#define NPTS   8192
#define TPB    512
#define QPT    8                 // queries per thread (4 packed f32x2 pairs)
#define QTILE  (TPB*QPT)         // 4096 queries per block
#define NTILE  (NPTS/QTILE)      // 2
#define NSEG   16                // db segments
#define SEGPTS (NPTS/NSEG)       // 512
#define NBLK   (NTILE*NSEG*4)    // 128 blocks (1/SM)

// Scratch (no allocs allowed)
__device__ float        g_pmin[4][NSEG][NPTS]; // [dir+2*part][seg][query] = qnorm+min
__device__ unsigned int g_count;               // zero-init; tail resets -> replay-safe

__device__ __forceinline__ unsigned long long pack2(float lo, float hi) {
    unsigned long long r;
    asm("mov.b64 %0, {%1, %2};" : "=l"(r)
        : "r"(__float_as_uint(lo)), "r"(__float_as_uint(hi)));
    return r;
}
__device__ __forceinline__ unsigned long long fma2(unsigned long long a,
                                                   unsigned long long b,
                                                   unsigned long long c) {
    unsigned long long d;
    asm("fma.rn.f32x2 %0, %1, %2, %3;" : "=l"(d) : "l"(a), "l"(b), "l"(c));
    return d;
}

// ---------------------------------------------------------------------------
// grid (NTILE*NSEG, dir, part) = 128 blocks of 512 thr (1/SM, 4 warps/SMSP).
// R13's f32x2 loop (2 broadcast LDS.128 + 12 FFMA2 + 8 FMNMX = 8 pairs/point)
// was latency-bound (issue 48%): the LDS->FFMA2 scoreboard stall was exposed.
// This version software-pipelines explicitly: A/B for j+1 are prefetched into
// rotated registers before computing j, giving the LDS a full body (~22 issue
// slots) to drain. smem padded +1 slot so no edge branches.
// dir0: query = T@cad, db = cam.  dir1: query = cam, db = T@cad.
// min_j |q-y|^2 = |q|^2 + min_j(|y|^2 - 2 q.y); -2 folded into staged coords.
// Ticket-elected last block merges db segments -> sqrt -> fp64 means.
// ---------------------------------------------------------------------------
__global__ void __launch_bounds__(TPB)
k_fused(const float* __restrict__ cam, const float* __restrict__ cad,
        const float* __restrict__ xyz, const float* __restrict__ rpy,
        const float* __restrict__ quat, const float* __restrict__ bt,
        const float* __restrict__ theta, const float* __restrict__ pw,
        float* __restrict__ out)
{
    __shared__ float4 sA[SEGPTS + 1];   // (-2x, -2x, -2y, -2y)  (+1: prefetch pad)
    __shared__ float4 sB[SEGPTS + 1];   // (-2z, -2z,  w,   w)
    __shared__ float  sxf[12];
    __shared__ double sr0[TPB], sr1[TPB];
    __shared__ int    s_last;

    const int part = blockIdx.z;
    const int dir  = blockIdx.y;
    const int tile = blockIdx.x >> 4;     // 0..1
    const int seg  = blockIdx.x & 15;     // 0..15
    const int tid  = threadIdx.x;
    const int dp   = dir + 2 * part;

    // --- per-block transform setup (thread 0; tiny) ---
    if (tid == 0) {
        float qa = quat[0], qb = quat[1], qc = quat[2], qd = quat[3];
        float qn = sqrtf(qa*qa + qb*qb + qc*qc + qd*qd);
        qa /= qn; qb /= qn; qc /= qn; qd /= qn;

        float B[16];
        B[0]  = 1.f - 2.f*qc*qc - 2.f*qd*qd;  B[1]  = 2.f*qb*qc - 2.f*qa*qd;        B[2]  = 2.f*qa*qc + 2.f*qb*qd;        B[3]  = bt[0];
        B[4]  = 2.f*qb*qc + 2.f*qa*qd;        B[5]  = 1.f - 2.f*qb*qb - 2.f*qd*qd;  B[6]  = 2.f*qc*qd - 2.f*qa*qb;        B[7]  = bt[1];
        B[8]  = 2.f*qb*qd - 2.f*qa*qc;        B[9]  = 2.f*qa*qb + 2.f*qc*qd;        B[10] = 1.f - 2.f*qb*qb - 2.f*qc*qc;  B[11] = bt[2];
        B[12] = 0.f; B[13] = 0.f; B[14] = 0.f; B[15] = 1.f;

        float ax = xyz[0], ay = xyz[1], az = xyz[2];
        float u  = rpy[0], v  = rpy[1], w  = rpy[2];
        float th = theta[0];
        float co = cosf(th), si = sinf(th), omc = 1.f - co;

        float R[16];
        R[0]  = u*u + (v*v + w*w)*co;   R[1]  = u*v*omc - w*si;          R[2]  = u*w*omc + v*si;
        R[3]  = (ax*(v*v + w*w) - u*(ay*v + az*w))*omc + (ay*w - az*v)*si;
        R[4]  = u*v*omc + w*si;         R[5]  = v*v + (u*u + w*w)*co;    R[6]  = v*w*omc - u*si;
        R[7]  = (ay*(u*u + w*w) - v*(ax*u + az*w))*omc + (az*u - ax*w)*si;
        R[8]  = u*w*omc - v*si;         R[9]  = v*w*omc + u*si;          R[10] = w*w + (u*u + v*v)*co;
        R[11] = (az*(u*u + v*v) - w*(ax*u + ay*v))*omc + (ax*v - ay*u)*si;
        R[12] = 0.f; R[13] = 0.f; R[14] = 0.f; R[15] = 1.f;

        float T[16];
        #pragma unroll
        for (int r = 0; r < 4; r++)
            #pragma unroll
            for (int c = 0; c < 4; c++) {
                float s = 0.f;
                #pragma unroll
                for (int k = 0; k < 4; k++) s += R[r*4 + k] * B[k*4 + c];
                T[r*4 + c] = s;
            }

        const float* X = (part == 0) ? B : T;
        #pragma unroll
        for (int i = 0; i < 12; i++) sxf[i] = X[i];

        if (blockIdx.x == 0 && dir == 0 && part == 0) {
            // out: [0]=all, [1]=base_obj, [2]=child_obj, [3..18]=base_T, [19..34]=rel_T
            #pragma unroll
            for (int i = 0; i < 16; i++) { out[3 + i] = B[i]; out[19 + i] = R[i]; }
        }
    }
    __syncthreads();

    const float t0 = sxf[0], t1 = sxf[1], t2  = sxf[2],  t3  = sxf[3];
    const float t4 = sxf[4], t5 = sxf[5], t6  = sxf[6],  t7  = sxf[7];
    const float t8 = sxf[8], t9 = sxf[9], t10 = sxf[10], t11 = sxf[11];

    const float* camP = cam + part * NPTS * 3;
    const float* cadP = cad + part * NPTS * 3;

    // --- stage this block's db segment, duplicated halves, -2 folded in ---
    for (int j = tid; j < SEGPTS; j += TPB) {
        int gj = seg * SEGPTS + j;
        float x, y, z;
        if (dir == 0) {
            x = camP[3*gj]; y = camP[3*gj + 1]; z = camP[3*gj + 2];
        } else {
            float a = cadP[3*gj], b = cadP[3*gj + 1], c = cadP[3*gj + 2];
            x = t0*a + t1*b + t2*c  + t3;
            y = t4*a + t5*b + t6*c  + t7;
            z = t8*a + t9*b + t10*c + t11;
        }
        float w  = x*x + y*y + z*z;
        float nx = -2.f*x, ny = -2.f*y, nz = -2.f*z;
        sA[j] = make_float4(nx, nx, ny, ny);
        sB[j] = make_float4(nz, nz, w,  w);
    }
    if (tid == 0) {   // pad slot (read by the last prefetch, never used)
        sA[SEGPTS] = make_float4(0.f, 0.f, 0.f, 0.f);
        sB[SEGPTS] = make_float4(0.f, 0.f, 0.f, 0.f);
    }

    // --- load 8 queries, pack as 4 f32x2 pairs ---
    float qn[QPT], m[QPT];
    unsigned long long qx2[4], qy2[4], qz2[4];
    {
        float qx[QPT], qy[QPT], qz[QPT];
        #pragma unroll
        for (int k = 0; k < QPT; k++) {
            const int q = tile * QTILE + k * TPB + tid;
            const float* src = (dir == 0) ? cadP : camP;
            float x = src[3*q], y = src[3*q + 1], z = src[3*q + 2];
            if (dir == 0) {
                qx[k] = t0*x + t1*y + t2*z  + t3;
                qy[k] = t4*x + t5*y + t6*z  + t7;
                qz[k] = t8*x + t9*y + t10*z + t11;
            } else { qx[k] = x; qy[k] = y; qz[k] = z; }
            qn[k] = qx[k]*qx[k] + qy[k]*qy[k] + qz[k]*qz[k];
            m[k]  = 3.4e38f;
        }
        #pragma unroll
        for (int p = 0; p < 4; p++) {
            qx2[p] = pack2(qx[2*p], qx[2*p + 1]);
            qy2[p] = pack2(qy[2*p], qy[2*p + 1]);
            qz2[p] = pack2(qz[2*p], qz[2*p + 1]);
        }
    }
    __syncthreads();

    // --- main loop, software-pipelined: prefetch j+1 while computing j ---
    {
        ulonglong2 A0 = *reinterpret_cast<const ulonglong2*>(&sA[0]);
        ulonglong2 B0 = *reinterpret_cast<const ulonglong2*>(&sB[0]);
        #pragma unroll 4
        for (int j = 0; j < SEGPTS; j++) {
            const ulonglong2 A1 = *reinterpret_cast<const ulonglong2*>(&sA[j + 1]);
            const ulonglong2 B1 = *reinterpret_cast<const ulonglong2*>(&sB[j + 1]);
            #pragma unroll
            for (int p = 0; p < 4; p++) {
                unsigned long long t = fma2(qz2[p], B0.x, B0.y);
                t = fma2(qy2[p], A0.y, t);
                t = fma2(qx2[p], A0.x, t);
                unsigned int lo, hi;
                asm("mov.b64 {%0, %1}, %2;" : "=r"(lo), "=r"(hi) : "l"(t));
                m[2*p]     = fminf(m[2*p],     __uint_as_float(lo));
                m[2*p + 1] = fminf(m[2*p + 1], __uint_as_float(hi));
            }
            A0 = A1; B0 = B1;
        }
    }

    // partial results (can be tiny-negative; clamped in tail)
    #pragma unroll
    for (int k = 0; k < QPT; k++) {
        const int q = tile * QTILE + k * TPB + tid;
        g_pmin[dp][seg][q] = qn[k] + m[k];
    }

    // --- ticket: last block reduces everything ---
    __threadfence();
    if (tid == 0) {
        unsigned int ticket = atomicAdd(&g_count, 1u);
        s_last = (ticket == NBLK - 1) ? 1 : 0;
    }
    __syncthreads();
    if (!s_last) return;

    __threadfence();
    double a0 = 0.0, a1 = 0.0;
    const int NG = NPTS / 4;                 // float4 groups per (dp,seg)
    for (int i = tid; i < 4 * NG; i += TPB) {
        const int d  = i / NG;
        const int qg = i % NG;
        const float4* base = reinterpret_cast<const float4*>(&g_pmin[d][0][0]);
        float4 v = base[qg];
        #pragma unroll
        for (int s = 1; s < NSEG; s++) {
            float4 u = base[s * NG + qg];
            v.x = fminf(v.x, u.x); v.y = fminf(v.y, u.y);
            v.z = fminf(v.z, u.z); v.w = fminf(v.w, u.w);
        }
        double dd = (double)sqrtf(fmaxf(v.x, 0.f))
                  + (double)sqrtf(fmaxf(v.y, 0.f))
                  + (double)sqrtf(fmaxf(v.z, 0.f))
                  + (double)sqrtf(fmaxf(v.w, 0.f));
        if (d < 2) a0 += dd; else a1 += dd;
    }
    sr0[tid] = a0; sr1[tid] = a1;
    __syncthreads();
    for (int s = TPB / 2; s > 0; s >>= 1) {
        if (tid < s) { sr0[tid] += sr0[tid + s]; sr1[tid] += sr1[tid + s]; }
        __syncthreads();
    }
    if (tid == 0) {
        double obj0 = sr0[0] / (double)NPTS;   // base part
        double obj1 = sr1[0] / (double)NPTS;   // child part
        out[1] = (float)obj0;
        out[2] = (float)obj1;
        out[0] = (float)(((double)pw[0] * obj0 + (double)pw[1] * obj1) / 2.0);
        g_count = 0;   // reset for next graph replay
    }
}

// ---------------------------------------------------------------------------
extern "C" void kernel_launch(void* const* d_in, const int* in_sizes, int n_in,
                              void* d_out, int out_size)
{
    const float* cam  = (const float*)d_in[0];  // camera_pts [2,8192,3]
    const float* cad  = (const float*)d_in[1];  // cad_pts    [2,8192,3]
    const float* xyz  = (const float*)d_in[2];  // [1,3]
    const float* rpy  = (const float*)d_in[3];  // [1,3]
    const float* pw   = (const float*)d_in[4];  // [2]
    const float* quat = (const float*)d_in[5];  // [4]
    const float* bt   = (const float*)d_in[6];  // [3,1]
    const float* th   = (const float*)d_in[7];  // [1]
    float* out = (float*)d_out;

    dim3 grid(NTILE * NSEG, 2, 2);   // 128 blocks of 512 thr (1 per SM)
    k_fused<<<grid, TPB>>>(cam, cad, xyz, rpy, quat, bt, th, pw, out);
}